// round 12
// baseline (speedup 1.0000x reference)
#include <cuda_runtime.h>
#include <cuda_bf16.h>
#include <math.h>
#include <stdint.h>

#define BATCH 16384
#define SEQ   50
#define DIM   300
#define HID   32
#define OUTC  2
#define VOCAB 400000

// allocation-free scratch
__device__ uint32_t g_E2[(size_t)VOCAB * (HID / 2)];   // bf16x2 table, 25.6 MB
__device__ float4   g_part[BATCH / 8];                 // per-CTA {m0,m1,s0,s1}
__device__ unsigned g_done;                            // gather completion ctr

// ---------------------------------------------------------------------------
// Pass A: E2[v][j] = sum_d emb[v][d] * Vw[j][d]   (400000x300 @ 300x32)
// tf32 mma.sync, 5-stage cp.async.bulk ring, 148 persistent CTAs x 256 thr,
// B fragments in registers, bf16x2 output.
// R12: emb bulk loads use L2::evict_first (read-once stream), E2 stores use
// L2::evict_last (pin the 25.6MB table in L2 for the gather pass).
// ---------------------------------------------------------------------------
#define TILE_R     32
#define KSTEPS     38
#define NT32       (VOCAB / TILE_R)          // 12500 tiles
#define GRID       148
#define NSTAGE     5
#define TILE_ELEMS (TILE_R * DIM)            // 9600 floats
#define TILE_BYTES (TILE_ELEMS * 4)          // 38400 B
#define PAD_ELEMS  16
#define MBAR_OFF   (NSTAGE * TILE_ELEMS + PAD_ELEMS)
#define SMEM_BYTES ((MBAR_OFF + 20) * 4)

__device__ __forceinline__ uint32_t smem_u32(const void* p) {
    return (uint32_t)__cvta_generic_to_shared(p);
}
__device__ __forceinline__ void mbar_init(uint32_t mbar, uint32_t cnt) {
    asm volatile("mbarrier.init.shared::cta.b64 [%0], %1;" :: "r"(mbar), "r"(cnt) : "memory");
}
__device__ __forceinline__ void mbar_expect_tx(uint32_t mbar, uint32_t bytes) {
    asm volatile("mbarrier.arrive.expect_tx.shared::cta.b64 _, [%0], %1;"
                 :: "r"(mbar), "r"(bytes) : "memory");
}
__device__ __forceinline__ void mbar_arrive(uint32_t mbar) {
    asm volatile("mbarrier.arrive.release.cta.shared::cta.b64 _, [%0];"
                 :: "r"(mbar) : "memory");
}
__device__ __forceinline__ void mbar_wait(uint32_t mbar, uint32_t parity) {
    asm volatile(
        "{\n\t"
        ".reg .pred P;\n\t"
        "WAIT_%=: \n\t"
        "mbarrier.try_wait.parity.acquire.cta.shared::cta.b64 P, [%0], %1, 0x989680;\n\t"
        "@P bra.uni DONE_%=;\n\t"
        "bra.uni WAIT_%=;\n\t"
        "DONE_%=: \n\t"
        "}"
        :: "r"(mbar), "r"(parity) : "memory");
}
__device__ __forceinline__ uint64_t policy_evict_first() {
    uint64_t pol;
    asm("createpolicy.fractional.L2::evict_first.b64 %0, 1.0;" : "=l"(pol));
    return pol;
}
__device__ __forceinline__ uint64_t policy_evict_last() {
    uint64_t pol;
    asm("createpolicy.fractional.L2::evict_last.b64 %0, 1.0;" : "=l"(pol));
    return pol;
}
__device__ __forceinline__ void bulk_copy_hint(uint32_t dst, const void* src,
                                               uint32_t bytes, uint32_t mbar,
                                               uint64_t pol) {
    asm volatile(
        "cp.async.bulk.shared::cta.global.mbarrier::complete_tx::bytes.L2::cache_hint "
        "[%0], [%1], %2, [%3], %4;"
        :: "r"(dst), "l"(src), "r"(bytes), "r"(mbar), "l"(pol) : "memory");
}
__device__ __forceinline__ void st_hint(uint32_t* p, uint32_t v, uint64_t pol) {
    asm volatile("st.global.L2::cache_hint.b32 [%0], %1, %2;"
                 :: "l"(p), "r"(v), "l"(pol) : "memory");
}
__device__ __forceinline__ void mma_tf32(
    float acc[4], uint32_t a0, uint32_t a1, uint32_t a2, uint32_t a3,
    uint32_t b0, uint32_t b1)
{
    asm volatile(
        "mma.sync.aligned.m16n8k8.row.col.f32.tf32.tf32.f32 "
        "{%0,%1,%2,%3}, {%4,%5,%6,%7}, {%8,%9}, {%0,%1,%2,%3};\n"
        : "+f"(acc[0]), "+f"(acc[1]), "+f"(acc[2]), "+f"(acc[3])
        : "r"(a0), "r"(a1), "r"(a2), "r"(a3), "r"(b0), "r"(b1));
}
__device__ __forceinline__ uint32_t pack_bf16x2(float lo, float hi) {
    __nv_bfloat162 v = __float22bfloat162_rn(make_float2(lo, hi));
    return *reinterpret_cast<uint32_t*>(&v);
}

__global__ __launch_bounds__(256) void project_kernel(
    const float* __restrict__ emb,
    const float* __restrict__ Vw)
{
    extern __shared__ float smem[];
    const uint32_t mbarBase  = smem_u32(smem + MBAR_OFF);   // full[0..4]
    const uint32_t emptyBase = mbarBase + NSTAGE * 8;       // empty[0..4]

    const int tid  = threadIdx.x;
    const int warp = tid >> 5;
    const int lane = tid & 31;
    const int g4   = lane >> 2;
    const int tg   = lane & 3;

    const int warpRow = warp >> 2;
    const int colQuad = warp & 3;
    const int aRow    = warpRow * 16 + g4;

    if (blockIdx.x == 0 && tid == 0) g_done = 0;   // reset gather's counter

    const uint64_t polF = policy_evict_first();
    const uint64_t polL = policy_evict_last();

    if (tid == 0) {
        #pragma unroll
        for (int i = 0; i < NSTAGE; i++) {
            mbar_init(mbarBase  + i * 8, 1);
            mbar_init(emptyBase + i * 8, 8);
        }
        asm volatile("fence.proxy.async.shared::cta;" ::: "memory");
    }
    if (tid < PAD_ELEMS)
        smem[NSTAGE * TILE_ELEMS + tid] = 0.0f;
    __syncthreads();

    const int bid = blockIdx.x;

    if (tid == 0) {
        #pragma unroll
        for (int s = 0; s < NSTAGE; s++) {
            int tt = bid + s * GRID;
            if (tt < NT32) {
                mbar_expect_tx(mbarBase + s * 8, TILE_BYTES);
                bulk_copy_hint(smem_u32(smem + s * TILE_ELEMS),
                               emb + (size_t)tt * TILE_ELEMS, TILE_BYTES,
                               mbarBase + s * 8, polF);
            }
        }
    }

    // B fragments straight from gmem into registers (once)
    uint2 breg[KSTEPS];
    {
        const int n = colQuad * 8 + g4;
        const float* vwr = Vw + n * DIM;
        #pragma unroll
        for (int ks = 0; ks < KSTEPS; ks++) {
            int k = ks * 8 + tg;
            breg[ks].x = (k     < DIM) ? __float_as_uint(vwr[k])     : 0u;
            breg[ks].y = (k + 4 < DIM) ? __float_as_uint(vwr[k + 4]) : 0u;
        }
    }

    uint32_t ph0 = 0, ph1 = 0, ph2 = 0, ph3 = 0, ph4 = 0;
    uint32_t pe0 = 0, pe1 = 0, pe2 = 0, pe3 = 0, pe4 = 0;

    int t = bid;
    while (t < NT32) {
        #pragma unroll
        for (int s = 0; s < NSTAGE; s++) {
            if (t < NT32) {
                const uint32_t fullb  = mbarBase  + s * 8;
                const uint32_t emptyb = emptyBase + s * 8;

                uint32_t phv = (s == 0) ? ph0 : (s == 1) ? ph1 : (s == 2) ? ph2
                             : (s == 3) ? ph3 : ph4;
                mbar_wait(fullb, phv);
                if      (s == 0) ph0 ^= 1;
                else if (s == 1) ph1 ^= 1;
                else if (s == 2) ph2 ^= 1;
                else if (s == 3) ph3 ^= 1;
                else             ph4 ^= 1;

                const uint32_t* A =
                    (const uint32_t*)(smem + s * TILE_ELEMS) + aRow * DIM + tg;

                float accE[4] = {0.f, 0.f, 0.f, 0.f};
                float accO[4] = {0.f, 0.f, 0.f, 0.f};

                #pragma unroll
                for (int ks = 0; ks < KSTEPS; ks += 2) {
                    {
                        const uint32_t* Ap = A + ks * 8;
                        mma_tf32(accE, Ap[0], Ap[8 * DIM], Ap[4], Ap[8 * DIM + 4],
                                 breg[ks].x, breg[ks].y);
                    }
                    {
                        const uint32_t* Ap = A + (ks + 1) * 8;
                        mma_tf32(accO, Ap[0], Ap[8 * DIM], Ap[4], Ap[8 * DIM + 4],
                                 breg[ks + 1].x, breg[ks + 1].y);
                    }
                }

                if (lane == 0) mbar_arrive(emptyb);

                // store 16x8 per warp as bf16x2, pinned in L2 (evict_last)
                int r0  = t * TILE_R + warpRow * 16 + g4;
                int cp  = colQuad * 4 + tg;
                st_hint(&g_E2[(size_t)r0 * (HID / 2) + cp],
                        pack_bf16x2(accE[0] + accO[0], accE[1] + accO[1]), polL);
                st_hint(&g_E2[(size_t)(r0 + 8) * (HID / 2) + cp],
                        pack_bf16x2(accE[2] + accO[2], accE[3] + accO[3]), polL);

                int tload = t + NSTAGE * GRID;
                if (tid == 0 && tload < NT32) {
                    uint32_t pev = (s == 0) ? pe0 : (s == 1) ? pe1 : (s == 2) ? pe2
                                 : (s == 3) ? pe3 : pe4;
                    mbar_wait(emptyb, pev);
                    if      (s == 0) pe0 ^= 1;
                    else if (s == 1) pe1 ^= 1;
                    else if (s == 2) pe2 ^= 1;
                    else if (s == 3) pe3 ^= 1;
                    else             pe4 ^= 1;
                    mbar_expect_tx(fullb, TILE_BYTES);
                    bulk_copy_hint(smem_u32(smem + s * TILE_ELEMS),
                                   emb + (size_t)tload * TILE_ELEMS, TILE_BYTES,
                                   fullb, polF);
                }
                t += GRID;
            }
        }
    }
}

// ---------------------------------------------------------------------------
// Pass B (fused): gather bf16 E2, mean-pool, relu head -> logits,
// per-CTA LSE partial, then the LAST CTA combines all partials (fixed order,
// deterministic) and applies log-softmax in place. No third kernel.
// Lane layout: grp = lane>>3 (which of 4 tokens per step), hp = lane&7
// (uint2 within the 64B row). 12 steps x 4 tokens + 2-token tail.
// ---------------------------------------------------------------------------
__global__ __launch_bounds__(256) void gather_kernel(
    const int*   __restrict__ tokens,
    const float* __restrict__ Vb,
    const float* __restrict__ Ww,
    const float* __restrict__ Wb,
    float*       __restrict__ out)
{
    __shared__ float2 sE[8];
    __shared__ bool   sLast;
    __shared__ float2 redm[256];
    __shared__ float2 reds[256];

    const int warp = threadIdx.x >> 5;
    const int b    = blockIdx.x * 8 + warp;
    const int lane = threadIdx.x & 31;
    const int grp  = lane >> 3;
    const int hp   = lane & 7;

    const uint2* E2v = (const uint2*)g_E2;    // 8 uint2 per row

    int t0 = tokens[b * SEQ + lane];
    int t1 = (lane < SEQ - 32) ? tokens[b * SEQ + 32 + lane] : 0;

    float4 acc = make_float4(0.f, 0.f, 0.f, 0.f);
    #pragma unroll
    for (int i = 0; i < 12; i++) {
        int idx = 4 * i + grp;
        int tok = (i < 8) ? __shfl_sync(0xffffffffu, t0, idx)
                          : __shfl_sync(0xffffffffu, t1, idx - 32);
        uint2 raw = __ldg(&E2v[(size_t)tok * 8 + hp]);
        float2 lo = __bfloat1622float2(*reinterpret_cast<__nv_bfloat162*>(&raw.x));
        float2 hi = __bfloat1622float2(*reinterpret_cast<__nv_bfloat162*>(&raw.y));
        acc.x += lo.x; acc.y += lo.y; acc.z += hi.x; acc.w += hi.y;
    }
    // tail: tokens 48, 49 handled by grp 0/1
    {
        int tok = __shfl_sync(0xffffffffu, t1, 16 + (grp & 1));
        if (grp < 2) {
            uint2 raw = __ldg(&E2v[(size_t)tok * 8 + hp]);
            float2 lo = __bfloat1622float2(*reinterpret_cast<__nv_bfloat162*>(&raw.x));
            float2 hi = __bfloat1622float2(*reinterpret_cast<__nv_bfloat162*>(&raw.y));
            acc.x += lo.x; acc.y += lo.y; acc.z += hi.x; acc.w += hi.y;
        }
    }

    // combine the 4 token groups (lanes {l, l^8, l^16, l^24} share hp)
    #pragma unroll
    for (int off = 8; off <= 16; off <<= 1) {
        acc.x += __shfl_xor_sync(0xffffffffu, acc.x, off);
        acc.y += __shfl_xor_sync(0xffffffffu, acc.y, off);
        acc.z += __shfl_xor_sync(0xffffffffu, acc.z, off);
        acc.w += __shfl_xor_sync(0xffffffffu, acc.w, off);
    }

    const float inv = 1.0f / (float)SEQ;
    float4 vb = ((const float4*)Vb)[hp];
    float h0 = fmaxf(acc.x * inv + vb.x, 0.f);
    float h1 = fmaxf(acc.y * inv + vb.y, 0.f);
    float h2 = fmaxf(acc.z * inv + vb.z, 0.f);
    float h3 = fmaxf(acc.w * inv + vb.w, 0.f);

    float4 w0 = ((const float4*)Ww)[hp];
    float4 w1 = ((const float4*)(Ww + HID))[hp];
    float p0 = h0 * w0.x + h1 * w0.y + h2 * w0.z + h3 * w0.w;
    float p1 = h0 * w1.x + h1 * w1.y + h2 * w1.z + h3 * w1.w;
    #pragma unroll
    for (int off = 4; off; off >>= 1) {
        p0 += __shfl_xor_sync(0xffffffffu, p0, off);
        p1 += __shfl_xor_sync(0xffffffffu, p1, off);
    }

    float e0 = p0 + Wb[0];
    float e1 = p1 + Wb[1];
    if (lane == 0) {
        out[b * OUTC + 0] = e0;
        out[b * OUTC + 1] = e1;
        sE[warp] = make_float2(e0, e1);
    }
    __syncthreads();

    // warp 0: per-CTA max + expsum over the 8 rows -> g_part
    if (warp == 0) {
        float v0 = -1e30f, v1 = -1e30f;
        if (lane < 8) { v0 = sE[lane].x; v1 = sE[lane].y; }
        float m0 = v0, m1 = v1;
        #pragma unroll
        for (int off = 4; off; off >>= 1) {
            m0 = fmaxf(m0, __shfl_xor_sync(0xffffffffu, m0, off));
            m1 = fmaxf(m1, __shfl_xor_sync(0xffffffffu, m1, off));
        }
        float s0 = (lane < 8) ? expf(v0 - m0) : 0.f;
        float s1 = (lane < 8) ? expf(v1 - m1) : 0.f;
        #pragma unroll
        for (int off = 4; off; off >>= 1) {
            s0 += __shfl_xor_sync(0xffffffffu, s0, off);
            s1 += __shfl_xor_sync(0xffffffffu, s1, off);
        }
        if (lane == 0)
            g_part[blockIdx.x] = make_float4(m0, m1, s0, s1);
    }
    __syncthreads();

    // completion counter; last CTA does the global LSE + apply
    if (threadIdx.x == 0) {
        __threadfence();                               // release partials + out
        unsigned n = atomicAdd(&g_done, 1u);
        sLast = (n == (unsigned)(gridDim.x - 1));
    }
    __syncthreads();
    if (!sLast) return;

    __threadfence();                                   // acquire everyone's writes
    const int tid = threadIdx.x;

    // 2048 partials, 8 per thread, fixed order
    float m0 = -1e30f, m1 = -1e30f;
    float4 loc[8];
    #pragma unroll
    for (int j = 0; j < 8; j++) {
        loc[j] = g_part[tid * 8 + j];
        m0 = fmaxf(m0, loc[j].x);
        m1 = fmaxf(m1, loc[j].y);
    }
    redm[tid] = make_float2(m0, m1);
    __syncthreads();
    for (int s = 128; s; s >>= 1) {
        if (tid < s) {
            redm[tid].x = fmaxf(redm[tid].x, redm[tid + s].x);
            redm[tid].y = fmaxf(redm[tid].y, redm[tid + s].y);
        }
        __syncthreads();
    }
    const float M0 = redm[0].x, M1 = redm[0].y;

    float s0 = 0.f, s1 = 0.f;
    #pragma unroll
    for (int j = 0; j < 8; j++) {
        s0 += loc[j].z * expf(loc[j].x - M0);
        s1 += loc[j].w * expf(loc[j].y - M1);
    }
    reds[tid] = make_float2(s0, s1);
    __syncthreads();
    for (int s = 128; s; s >>= 1) {
        if (tid < s) {
            reds[tid].x += reds[tid + s].x;
            reds[tid].y += reds[tid + s].y;
        }
        __syncthreads();
    }
    const float l0 = M0 + logf(reds[0].x);
    const float l1 = M1 + logf(reds[0].y);

    for (int r = tid; r < BATCH; r += 256) {
        float2 v = reinterpret_cast<float2*>(out)[r];
        v.x -= l0;
        v.y -= l1;
        reinterpret_cast<float2*>(out)[r] = v;
    }
}

extern "C" void kernel_launch(void* const* d_in, const int* in_sizes, int n_in,
                              void* d_out, int out_size)
{
    const int*   tokens = (const int*)  d_in[0];
    const float* emb    = (const float*)d_in[1];
    const float* Vw     = (const float*)d_in[2];
    const float* Vb     = (const float*)d_in[3];
    const float* Ww     = (const float*)d_in[4];
    const float* Wb     = (const float*)d_in[5];
    float* out = (float*)d_out;

    cudaFuncSetAttribute(project_kernel,
                         cudaFuncAttributeMaxDynamicSharedMemorySize, SMEM_BYTES);

    project_kernel<<<GRID, 256, SMEM_BYTES>>>(emb, Vw);
    gather_kernel<<<BATCH / 8, 256>>>(tokens, Vb, Ww, Wb, out);
}

// round 13
// speedup vs baseline: 1.0435x; 1.0435x over previous
#include <cuda_runtime.h>
#include <cuda_bf16.h>
#include <math.h>
#include <stdint.h>

#define BATCH 16384
#define SEQ   50
#define DIM   300
#define HID   32
#define OUTC  2
#define VOCAB 400000

// allocation-free scratch
__device__ uint32_t g_E2[(size_t)VOCAB * (HID / 2)];   // bf16x2 table, 25.6 MB
__device__ float4   g_part[BATCH / 8];                 // per-CTA {m0,m1,s0,s1}
__device__ float    g_lse[2];                          // global logsumexp
__device__ unsigned g_done;                            // gather completion ctr

// ---------------------------------------------------------------------------
// Pass A: E2[v][j] = sum_d emb[v][d] * Vw[j][d]   (400000x300 @ 300x32)
// tf32 mma.sync, 5-stage cp.async.bulk ring, 148 persistent CTAs x 256 thr,
// B fragments in registers, bf16x2 output. emb loads L2::evict_first,
// E2 stores L2::evict_last. (At its HBM floor: 505.6MB @ ~6.33TB/s.)
// ---------------------------------------------------------------------------
#define TILE_R     32
#define KSTEPS     38
#define NT32       (VOCAB / TILE_R)          // 12500 tiles
#define GRID       148
#define NSTAGE     5
#define TILE_ELEMS (TILE_R * DIM)            // 9600 floats
#define TILE_BYTES (TILE_ELEMS * 4)          // 38400 B
#define PAD_ELEMS  16
#define MBAR_OFF   (NSTAGE * TILE_ELEMS + PAD_ELEMS)
#define SMEM_BYTES ((MBAR_OFF + 20) * 4)

__device__ __forceinline__ uint32_t smem_u32(const void* p) {
    return (uint32_t)__cvta_generic_to_shared(p);
}
__device__ __forceinline__ void mbar_init(uint32_t mbar, uint32_t cnt) {
    asm volatile("mbarrier.init.shared::cta.b64 [%0], %1;" :: "r"(mbar), "r"(cnt) : "memory");
}
__device__ __forceinline__ void mbar_expect_tx(uint32_t mbar, uint32_t bytes) {
    asm volatile("mbarrier.arrive.expect_tx.shared::cta.b64 _, [%0], %1;"
                 :: "r"(mbar), "r"(bytes) : "memory");
}
__device__ __forceinline__ void mbar_arrive(uint32_t mbar) {
    asm volatile("mbarrier.arrive.release.cta.shared::cta.b64 _, [%0];"
                 :: "r"(mbar) : "memory");
}
__device__ __forceinline__ void mbar_wait(uint32_t mbar, uint32_t parity) {
    asm volatile(
        "{\n\t"
        ".reg .pred P;\n\t"
        "WAIT_%=: \n\t"
        "mbarrier.try_wait.parity.acquire.cta.shared::cta.b64 P, [%0], %1, 0x989680;\n\t"
        "@P bra.uni DONE_%=;\n\t"
        "bra.uni WAIT_%=;\n\t"
        "DONE_%=: \n\t"
        "}"
        :: "r"(mbar), "r"(parity) : "memory");
}
__device__ __forceinline__ uint64_t policy_evict_first() {
    uint64_t pol;
    asm("createpolicy.fractional.L2::evict_first.b64 %0, 1.0;" : "=l"(pol));
    return pol;
}
__device__ __forceinline__ uint64_t policy_evict_last() {
    uint64_t pol;
    asm("createpolicy.fractional.L2::evict_last.b64 %0, 1.0;" : "=l"(pol));
    return pol;
}
__device__ __forceinline__ void bulk_copy_hint(uint32_t dst, const void* src,
                                               uint32_t bytes, uint32_t mbar,
                                               uint64_t pol) {
    asm volatile(
        "cp.async.bulk.shared::cta.global.mbarrier::complete_tx::bytes.L2::cache_hint "
        "[%0], [%1], %2, [%3], %4;"
        :: "r"(dst), "l"(src), "r"(bytes), "r"(mbar), "l"(pol) : "memory");
}
__device__ __forceinline__ void st_hint(uint32_t* p, uint32_t v, uint64_t pol) {
    asm volatile("st.global.L2::cache_hint.b32 [%0], %1, %2;"
                 :: "l"(p), "r"(v), "l"(pol) : "memory");
}
__device__ __forceinline__ void mma_tf32(
    float acc[4], uint32_t a0, uint32_t a1, uint32_t a2, uint32_t a3,
    uint32_t b0, uint32_t b1)
{
    asm volatile(
        "mma.sync.aligned.m16n8k8.row.col.f32.tf32.tf32.f32 "
        "{%0,%1,%2,%3}, {%4,%5,%6,%7}, {%8,%9}, {%0,%1,%2,%3};\n"
        : "+f"(acc[0]), "+f"(acc[1]), "+f"(acc[2]), "+f"(acc[3])
        : "r"(a0), "r"(a1), "r"(a2), "r"(a3), "r"(b0), "r"(b1));
}
__device__ __forceinline__ uint32_t pack_bf16x2(float lo, float hi) {
    __nv_bfloat162 v = __float22bfloat162_rn(make_float2(lo, hi));
    return *reinterpret_cast<uint32_t*>(&v);
}

__global__ __launch_bounds__(256) void project_kernel(
    const float* __restrict__ emb,
    const float* __restrict__ Vw)
{
    extern __shared__ float smem[];
    const uint32_t mbarBase  = smem_u32(smem + MBAR_OFF);   // full[0..4]
    const uint32_t emptyBase = mbarBase + NSTAGE * 8;       // empty[0..4]

    const int tid  = threadIdx.x;
    const int warp = tid >> 5;
    const int lane = tid & 31;
    const int g4   = lane >> 2;
    const int tg   = lane & 3;

    const int warpRow = warp >> 2;
    const int colQuad = warp & 3;
    const int aRow    = warpRow * 16 + g4;

    if (blockIdx.x == 0 && tid == 0) g_done = 0;   // reset gather's counter

    const uint64_t polF = policy_evict_first();
    const uint64_t polL = policy_evict_last();

    if (tid == 0) {
        #pragma unroll
        for (int i = 0; i < NSTAGE; i++) {
            mbar_init(mbarBase  + i * 8, 1);
            mbar_init(emptyBase + i * 8, 8);
        }
        asm volatile("fence.proxy.async.shared::cta;" ::: "memory");
    }
    if (tid < PAD_ELEMS)
        smem[NSTAGE * TILE_ELEMS + tid] = 0.0f;
    __syncthreads();

    const int bid = blockIdx.x;

    if (tid == 0) {
        #pragma unroll
        for (int s = 0; s < NSTAGE; s++) {
            int tt = bid + s * GRID;
            if (tt < NT32) {
                mbar_expect_tx(mbarBase + s * 8, TILE_BYTES);
                bulk_copy_hint(smem_u32(smem + s * TILE_ELEMS),
                               emb + (size_t)tt * TILE_ELEMS, TILE_BYTES,
                               mbarBase + s * 8, polF);
            }
        }
    }

    // B fragments straight from gmem into registers (once)
    uint2 breg[KSTEPS];
    {
        const int n = colQuad * 8 + g4;
        const float* vwr = Vw + n * DIM;
        #pragma unroll
        for (int ks = 0; ks < KSTEPS; ks++) {
            int k = ks * 8 + tg;
            breg[ks].x = (k     < DIM) ? __float_as_uint(vwr[k])     : 0u;
            breg[ks].y = (k + 4 < DIM) ? __float_as_uint(vwr[k + 4]) : 0u;
        }
    }

    uint32_t ph0 = 0, ph1 = 0, ph2 = 0, ph3 = 0, ph4 = 0;
    uint32_t pe0 = 0, pe1 = 0, pe2 = 0, pe3 = 0, pe4 = 0;

    int t = bid;
    while (t < NT32) {
        #pragma unroll
        for (int s = 0; s < NSTAGE; s++) {
            if (t < NT32) {
                const uint32_t fullb  = mbarBase  + s * 8;
                const uint32_t emptyb = emptyBase + s * 8;

                uint32_t phv = (s == 0) ? ph0 : (s == 1) ? ph1 : (s == 2) ? ph2
                             : (s == 3) ? ph3 : ph4;
                mbar_wait(fullb, phv);
                if      (s == 0) ph0 ^= 1;
                else if (s == 1) ph1 ^= 1;
                else if (s == 2) ph2 ^= 1;
                else if (s == 3) ph3 ^= 1;
                else             ph4 ^= 1;

                const uint32_t* A =
                    (const uint32_t*)(smem + s * TILE_ELEMS) + aRow * DIM + tg;

                float accE[4] = {0.f, 0.f, 0.f, 0.f};
                float accO[4] = {0.f, 0.f, 0.f, 0.f};

                #pragma unroll
                for (int ks = 0; ks < KSTEPS; ks += 2) {
                    {
                        const uint32_t* Ap = A + ks * 8;
                        mma_tf32(accE, Ap[0], Ap[8 * DIM], Ap[4], Ap[8 * DIM + 4],
                                 breg[ks].x, breg[ks].y);
                    }
                    {
                        const uint32_t* Ap = A + (ks + 1) * 8;
                        mma_tf32(accO, Ap[0], Ap[8 * DIM], Ap[4], Ap[8 * DIM + 4],
                                 breg[ks + 1].x, breg[ks + 1].y);
                    }
                }

                if (lane == 0) mbar_arrive(emptyb);

                int r0  = t * TILE_R + warpRow * 16 + g4;
                int cp  = colQuad * 4 + tg;
                st_hint(&g_E2[(size_t)r0 * (HID / 2) + cp],
                        pack_bf16x2(accE[0] + accO[0], accE[1] + accO[1]), polL);
                st_hint(&g_E2[(size_t)(r0 + 8) * (HID / 2) + cp],
                        pack_bf16x2(accE[2] + accO[2], accE[3] + accO[3]), polL);

                int tload = t + NSTAGE * GRID;
                if (tid == 0 && tload < NT32) {
                    uint32_t pev = (s == 0) ? pe0 : (s == 1) ? pe1 : (s == 2) ? pe2
                                 : (s == 3) ? pe3 : pe4;
                    mbar_wait(emptyb, pev);
                    if      (s == 0) pe0 ^= 1;
                    else if (s == 1) pe1 ^= 1;
                    else if (s == 2) pe2 ^= 1;
                    else if (s == 3) pe3 ^= 1;
                    else             pe4 ^= 1;
                    mbar_expect_tx(fullb, TILE_BYTES);
                    bulk_copy_hint(smem_u32(smem + s * TILE_ELEMS),
                                   emb + (size_t)tload * TILE_ELEMS, TILE_BYTES,
                                   fullb, polF);
                }
                t += GRID;
            }
        }
    }
}

// ---------------------------------------------------------------------------
// Pass B: gather bf16 E2, mean-pool, relu head -> logits + per-CTA partial.
// Last CTA reduces the 2048 partials to the two global LSE SCALARS only
// (fixed order -> deterministic); the heavy apply loop lives in its own
// wide kernel (Pass C).
// ---------------------------------------------------------------------------
__global__ __launch_bounds__(256) void gather_kernel(
    const int*   __restrict__ tokens,
    const float* __restrict__ Vb,
    const float* __restrict__ Ww,
    const float* __restrict__ Wb,
    float*       __restrict__ out)
{
    __shared__ float2 sE[8];
    __shared__ bool   sLast;
    __shared__ float2 redm[256];
    __shared__ float2 reds[256];

    const int warp = threadIdx.x >> 5;
    const int b    = blockIdx.x * 8 + warp;
    const int lane = threadIdx.x & 31;
    const int grp  = lane >> 3;
    const int hp   = lane & 7;

    const uint2* E2v = (const uint2*)g_E2;    // 8 uint2 per row

    int t0 = tokens[b * SEQ + lane];
    int t1 = (lane < SEQ - 32) ? tokens[b * SEQ + 32 + lane] : 0;

    float4 acc = make_float4(0.f, 0.f, 0.f, 0.f);
    #pragma unroll
    for (int i = 0; i < 12; i++) {
        int idx = 4 * i + grp;
        int tok = (i < 8) ? __shfl_sync(0xffffffffu, t0, idx)
                          : __shfl_sync(0xffffffffu, t1, idx - 32);
        uint2 raw = __ldg(&E2v[(size_t)tok * 8 + hp]);
        float2 lo = __bfloat1622float2(*reinterpret_cast<__nv_bfloat162*>(&raw.x));
        float2 hi = __bfloat1622float2(*reinterpret_cast<__nv_bfloat162*>(&raw.y));
        acc.x += lo.x; acc.y += lo.y; acc.z += hi.x; acc.w += hi.y;
    }
    {   // tail: tokens 48, 49
        int tok = __shfl_sync(0xffffffffu, t1, 16 + (grp & 1));
        if (grp < 2) {
            uint2 raw = __ldg(&E2v[(size_t)tok * 8 + hp]);
            float2 lo = __bfloat1622float2(*reinterpret_cast<__nv_bfloat162*>(&raw.x));
            float2 hi = __bfloat1622float2(*reinterpret_cast<__nv_bfloat162*>(&raw.y));
            acc.x += lo.x; acc.y += lo.y; acc.z += hi.x; acc.w += hi.y;
        }
    }

    #pragma unroll
    for (int off = 8; off <= 16; off <<= 1) {
        acc.x += __shfl_xor_sync(0xffffffffu, acc.x, off);
        acc.y += __shfl_xor_sync(0xffffffffu, acc.y, off);
        acc.z += __shfl_xor_sync(0xffffffffu, acc.z, off);
        acc.w += __shfl_xor_sync(0xffffffffu, acc.w, off);
    }

    const float inv = 1.0f / (float)SEQ;
    float4 vb = ((const float4*)Vb)[hp];
    float h0 = fmaxf(acc.x * inv + vb.x, 0.f);
    float h1 = fmaxf(acc.y * inv + vb.y, 0.f);
    float h2 = fmaxf(acc.z * inv + vb.z, 0.f);
    float h3 = fmaxf(acc.w * inv + vb.w, 0.f);

    float4 w0 = ((const float4*)Ww)[hp];
    float4 w1 = ((const float4*)(Ww + HID))[hp];
    float p0 = h0 * w0.x + h1 * w0.y + h2 * w0.z + h3 * w0.w;
    float p1 = h0 * w1.x + h1 * w1.y + h2 * w1.z + h3 * w1.w;
    #pragma unroll
    for (int off = 4; off; off >>= 1) {
        p0 += __shfl_xor_sync(0xffffffffu, p0, off);
        p1 += __shfl_xor_sync(0xffffffffu, p1, off);
    }

    float e0 = p0 + Wb[0];
    float e1 = p1 + Wb[1];
    if (lane == 0) {
        out[b * OUTC + 0] = e0;
        out[b * OUTC + 1] = e1;
        sE[warp] = make_float2(e0, e1);
    }
    __syncthreads();

    if (warp == 0) {
        float v0 = -1e30f, v1 = -1e30f;
        if (lane < 8) { v0 = sE[lane].x; v1 = sE[lane].y; }
        float m0 = v0, m1 = v1;
        #pragma unroll
        for (int off = 4; off; off >>= 1) {
            m0 = fmaxf(m0, __shfl_xor_sync(0xffffffffu, m0, off));
            m1 = fmaxf(m1, __shfl_xor_sync(0xffffffffu, m1, off));
        }
        float s0 = (lane < 8) ? expf(v0 - m0) : 0.f;
        float s1 = (lane < 8) ? expf(v1 - m1) : 0.f;
        #pragma unroll
        for (int off = 4; off; off >>= 1) {
            s0 += __shfl_xor_sync(0xffffffffu, s0, off);
            s1 += __shfl_xor_sync(0xffffffffu, s1, off);
        }
        if (lane == 0)
            g_part[blockIdx.x] = make_float4(m0, m1, s0, s1);
    }
    __syncthreads();

    // completion counter; last CTA computes the LSE scalars only
    if (threadIdx.x == 0) {
        __threadfence();
        unsigned n = atomicAdd(&g_done, 1u);
        sLast = (n == (unsigned)(gridDim.x - 1));
    }
    __syncthreads();
    if (!sLast) return;

    __threadfence();
    const int tid = threadIdx.x;

    float m0 = -1e30f, m1 = -1e30f;
    float4 loc[8];
    #pragma unroll
    for (int j = 0; j < 8; j++) {
        loc[j] = g_part[tid * 8 + j];
        m0 = fmaxf(m0, loc[j].x);
        m1 = fmaxf(m1, loc[j].y);
    }
    redm[tid] = make_float2(m0, m1);
    __syncthreads();
    for (int s = 128; s; s >>= 1) {
        if (tid < s) {
            redm[tid].x = fmaxf(redm[tid].x, redm[tid + s].x);
            redm[tid].y = fmaxf(redm[tid].y, redm[tid + s].y);
        }
        __syncthreads();
    }
    const float M0 = redm[0].x, M1 = redm[0].y;

    float s0 = 0.f, s1 = 0.f;
    #pragma unroll
    for (int j = 0; j < 8; j++) {
        s0 += loc[j].z * expf(loc[j].x - M0);
        s1 += loc[j].w * expf(loc[j].y - M1);
    }
    reds[tid] = make_float2(s0, s1);
    __syncthreads();
    for (int s = 128; s; s >>= 1) {
        if (tid < s) {
            reds[tid].x += reds[tid + s].x;
            reds[tid].y += reds[tid + s].y;
        }
        __syncthreads();
    }
    if (tid == 0) {
        g_lse[0] = M0 + logf(reds[0].x);
        g_lse[1] = M1 + logf(reds[0].y);
    }
}

// ---------------------------------------------------------------------------
// Pass C: wide parallel apply: out[b,c] -= lse[c]. 64 CTAs x 256 threads.
// ---------------------------------------------------------------------------
__global__ __launch_bounds__(256) void apply_kernel(float* __restrict__ out)
{
    const float l0 = g_lse[0];
    const float l1 = g_lse[1];
    const int   i  = blockIdx.x * 256 + threadIdx.x;   // 16384 float2 total
    float2 v = reinterpret_cast<float2*>(out)[i];
    v.x -= l0;
    v.y -= l1;
    reinterpret_cast<float2*>(out)[i] = v;
}

extern "C" void kernel_launch(void* const* d_in, const int* in_sizes, int n_in,
                              void* d_out, int out_size)
{
    const int*   tokens = (const int*)  d_in[0];
    const float* emb    = (const float*)d_in[1];
    const float* Vw     = (const float*)d_in[2];
    const float* Vb     = (const float*)d_in[3];
    const float* Ww     = (const float*)d_in[4];
    const float* Wb     = (const float*)d_in[5];
    float* out = (float*)d_out;

    cudaFuncSetAttribute(project_kernel,
                         cudaFuncAttributeMaxDynamicSharedMemorySize, SMEM_BYTES);

    project_kernel<<<GRID, 256, SMEM_BYTES>>>(emb, Vw);
    gather_kernel<<<BATCH / 8, 256>>>(tokens, Vb, Ww, Wb, out);
    apply_kernel<<<BATCH / 256, 256>>>(out);
}

// round 14
// speedup vs baseline: 1.0570x; 1.0130x over previous
#include <cuda_runtime.h>
#include <cuda_bf16.h>
#include <math.h>
#include <stdint.h>

#define BATCH 16384
#define SEQ   50
#define DIM   300
#define HID   32
#define OUTC  2
#define VOCAB 400000

// allocation-free scratch
__device__ uint32_t g_E2[(size_t)VOCAB * (HID / 2)];   // bf16x2 table, 25.6 MB
__device__ float4   g_part[BATCH / 16];                // per-CTA {m0,m1,s0,s1}
__device__ float    g_lse[2];                          // global logsumexp
__device__ unsigned g_done;                            // gather completion ctr

// ---------------------------------------------------------------------------
// Pass A: E2[v][j] = sum_d emb[v][d] * Vw[j][d]   (400000x300 @ 300x32)
// tf32 mma.sync, 5-stage cp.async.bulk ring, 148 persistent CTAs x 256 thr,
// B fragments in registers, bf16x2 output. emb loads L2::evict_first,
// E2 stores L2::evict_last. (At its HBM floor: 505.6MB @ ~6.2TB/s.)
// ---------------------------------------------------------------------------
#define TILE_R     32
#define KSTEPS     38
#define NT32       (VOCAB / TILE_R)          // 12500 tiles
#define GRID       148
#define NSTAGE     5
#define TILE_ELEMS (TILE_R * DIM)            // 9600 floats
#define TILE_BYTES (TILE_ELEMS * 4)          // 38400 B
#define PAD_ELEMS  16
#define MBAR_OFF   (NSTAGE * TILE_ELEMS + PAD_ELEMS)
#define SMEM_BYTES ((MBAR_OFF + 20) * 4)

__device__ __forceinline__ uint32_t smem_u32(const void* p) {
    return (uint32_t)__cvta_generic_to_shared(p);
}
__device__ __forceinline__ void mbar_init(uint32_t mbar, uint32_t cnt) {
    asm volatile("mbarrier.init.shared::cta.b64 [%0], %1;" :: "r"(mbar), "r"(cnt) : "memory");
}
__device__ __forceinline__ void mbar_expect_tx(uint32_t mbar, uint32_t bytes) {
    asm volatile("mbarrier.arrive.expect_tx.shared::cta.b64 _, [%0], %1;"
                 :: "r"(mbar), "r"(bytes) : "memory");
}
__device__ __forceinline__ void mbar_arrive(uint32_t mbar) {
    asm volatile("mbarrier.arrive.release.cta.shared::cta.b64 _, [%0];"
                 :: "r"(mbar) : "memory");
}
__device__ __forceinline__ void mbar_wait(uint32_t mbar, uint32_t parity) {
    asm volatile(
        "{\n\t"
        ".reg .pred P;\n\t"
        "WAIT_%=: \n\t"
        "mbarrier.try_wait.parity.acquire.cta.shared::cta.b64 P, [%0], %1, 0x989680;\n\t"
        "@P bra.uni DONE_%=;\n\t"
        "bra.uni WAIT_%=;\n\t"
        "DONE_%=: \n\t"
        "}"
        :: "r"(mbar), "r"(parity) : "memory");
}
__device__ __forceinline__ uint64_t policy_evict_first() {
    uint64_t pol;
    asm("createpolicy.fractional.L2::evict_first.b64 %0, 1.0;" : "=l"(pol));
    return pol;
}
__device__ __forceinline__ uint64_t policy_evict_last() {
    uint64_t pol;
    asm("createpolicy.fractional.L2::evict_last.b64 %0, 1.0;" : "=l"(pol));
    return pol;
}
__device__ __forceinline__ void bulk_copy_hint(uint32_t dst, const void* src,
                                               uint32_t bytes, uint32_t mbar,
                                               uint64_t pol) {
    asm volatile(
        "cp.async.bulk.shared::cta.global.mbarrier::complete_tx::bytes.L2::cache_hint "
        "[%0], [%1], %2, [%3], %4;"
        :: "r"(dst), "l"(src), "r"(bytes), "r"(mbar), "l"(pol) : "memory");
}
__device__ __forceinline__ void st_hint(uint32_t* p, uint32_t v, uint64_t pol) {
    asm volatile("st.global.L2::cache_hint.b32 [%0], %1, %2;"
                 :: "l"(p), "r"(v), "l"(pol) : "memory");
}
__device__ __forceinline__ void mma_tf32(
    float acc[4], uint32_t a0, uint32_t a1, uint32_t a2, uint32_t a3,
    uint32_t b0, uint32_t b1)
{
    asm volatile(
        "mma.sync.aligned.m16n8k8.row.col.f32.tf32.tf32.f32 "
        "{%0,%1,%2,%3}, {%4,%5,%6,%7}, {%8,%9}, {%0,%1,%2,%3};\n"
        : "+f"(acc[0]), "+f"(acc[1]), "+f"(acc[2]), "+f"(acc[3])
        : "r"(a0), "r"(a1), "r"(a2), "r"(a3), "r"(b0), "r"(b1));
}
__device__ __forceinline__ uint32_t pack_bf16x2(float lo, float hi) {
    __nv_bfloat162 v = __float22bfloat162_rn(make_float2(lo, hi));
    return *reinterpret_cast<uint32_t*>(&v);
}

__global__ __launch_bounds__(256) void project_kernel(
    const float* __restrict__ emb,
    const float* __restrict__ Vw)
{
    extern __shared__ float smem[];
    const uint32_t mbarBase  = smem_u32(smem + MBAR_OFF);   // full[0..4]
    const uint32_t emptyBase = mbarBase + NSTAGE * 8;       // empty[0..4]

    const int tid  = threadIdx.x;
    const int warp = tid >> 5;
    const int lane = tid & 31;
    const int g4   = lane >> 2;
    const int tg   = lane & 3;

    const int warpRow = warp >> 2;
    const int colQuad = warp & 3;
    const int aRow    = warpRow * 16 + g4;

    if (blockIdx.x == 0 && tid == 0) g_done = 0;   // reset gather's counter

    const uint64_t polF = policy_evict_first();
    const uint64_t polL = policy_evict_last();

    if (tid == 0) {
        #pragma unroll
        for (int i = 0; i < NSTAGE; i++) {
            mbar_init(mbarBase  + i * 8, 1);
            mbar_init(emptyBase + i * 8, 8);
        }
        asm volatile("fence.proxy.async.shared::cta;" ::: "memory");
    }
    if (tid < PAD_ELEMS)
        smem[NSTAGE * TILE_ELEMS + tid] = 0.0f;
    __syncthreads();

    const int bid = blockIdx.x;

    if (tid == 0) {
        #pragma unroll
        for (int s = 0; s < NSTAGE; s++) {
            int tt = bid + s * GRID;
            if (tt < NT32) {
                mbar_expect_tx(mbarBase + s * 8, TILE_BYTES);
                bulk_copy_hint(smem_u32(smem + s * TILE_ELEMS),
                               emb + (size_t)tt * TILE_ELEMS, TILE_BYTES,
                               mbarBase + s * 8, polF);
            }
        }
    }

    // B fragments straight from gmem into registers (once)
    uint2 breg[KSTEPS];
    {
        const int n = colQuad * 8 + g4;
        const float* vwr = Vw + n * DIM;
        #pragma unroll
        for (int ks = 0; ks < KSTEPS; ks++) {
            int k = ks * 8 + tg;
            breg[ks].x = (k     < DIM) ? __float_as_uint(vwr[k])     : 0u;
            breg[ks].y = (k + 4 < DIM) ? __float_as_uint(vwr[k + 4]) : 0u;
        }
    }

    uint32_t ph0 = 0, ph1 = 0, ph2 = 0, ph3 = 0, ph4 = 0;
    uint32_t pe0 = 0, pe1 = 0, pe2 = 0, pe3 = 0, pe4 = 0;

    int t = bid;
    while (t < NT32) {
        #pragma unroll
        for (int s = 0; s < NSTAGE; s++) {
            if (t < NT32) {
                const uint32_t fullb  = mbarBase  + s * 8;
                const uint32_t emptyb = emptyBase + s * 8;

                uint32_t phv = (s == 0) ? ph0 : (s == 1) ? ph1 : (s == 2) ? ph2
                             : (s == 3) ? ph3 : ph4;
                mbar_wait(fullb, phv);
                if      (s == 0) ph0 ^= 1;
                else if (s == 1) ph1 ^= 1;
                else if (s == 2) ph2 ^= 1;
                else if (s == 3) ph3 ^= 1;
                else             ph4 ^= 1;

                const uint32_t* A =
                    (const uint32_t*)(smem + s * TILE_ELEMS) + aRow * DIM + tg;

                float accE[4] = {0.f, 0.f, 0.f, 0.f};
                float accO[4] = {0.f, 0.f, 0.f, 0.f};

                #pragma unroll
                for (int ks = 0; ks < KSTEPS; ks += 2) {
                    {
                        const uint32_t* Ap = A + ks * 8;
                        mma_tf32(accE, Ap[0], Ap[8 * DIM], Ap[4], Ap[8 * DIM + 4],
                                 breg[ks].x, breg[ks].y);
                    }
                    {
                        const uint32_t* Ap = A + (ks + 1) * 8;
                        mma_tf32(accO, Ap[0], Ap[8 * DIM], Ap[4], Ap[8 * DIM + 4],
                                 breg[ks + 1].x, breg[ks + 1].y);
                    }
                }

                if (lane == 0) mbar_arrive(emptyb);

                int r0  = t * TILE_R + warpRow * 16 + g4;
                int cp  = colQuad * 4 + tg;
                st_hint(&g_E2[(size_t)r0 * (HID / 2) + cp],
                        pack_bf16x2(accE[0] + accO[0], accE[1] + accO[1]), polL);
                st_hint(&g_E2[(size_t)(r0 + 8) * (HID / 2) + cp],
                        pack_bf16x2(accE[2] + accO[2], accE[3] + accO[3]), polL);

                int tload = t + NSTAGE * GRID;
                if (tid == 0 && tload < NT32) {
                    uint32_t pev = (s == 0) ? pe0 : (s == 1) ? pe1 : (s == 2) ? pe2
                                 : (s == 3) ? pe3 : pe4;
                    mbar_wait(emptyb, pev);
                    if      (s == 0) pe0 ^= 1;
                    else if (s == 1) pe1 ^= 1;
                    else if (s == 2) pe2 ^= 1;
                    else if (s == 3) pe3 ^= 1;
                    else             pe4 ^= 1;
                    mbar_expect_tx(fullb, TILE_BYTES);
                    bulk_copy_hint(smem_u32(smem + s * TILE_ELEMS),
                                   emb + (size_t)tload * TILE_ELEMS, TILE_BYTES,
                                   fullb, polF);
                }
                t += GRID;
            }
        }
    }
}

// ---------------------------------------------------------------------------
// Pass B: gather bf16 E2, mean-pool, relu head -> logits + per-CTA partial.
// R14: 512 threads / 16 rows per CTA (grid 1024). Two-phase per warp:
// (1) resolve all 13 token indices, (2) issue all 13 E2 loads into a
// register array (MLP=13), (3) convert+accumulate. Last CTA reduces the
// 1024 partials to the two LSE scalars (fixed order, deterministic).
// ---------------------------------------------------------------------------
__global__ __launch_bounds__(512) void gather_kernel(
    const int*   __restrict__ tokens,
    const float* __restrict__ Vb,
    const float* __restrict__ Ww,
    const float* __restrict__ Wb,
    float*       __restrict__ out)
{
    __shared__ float2 sE[16];
    __shared__ bool   sLast;
    __shared__ float2 redm[512];
    __shared__ float2 reds[512];

    const int warp = threadIdx.x >> 5;          // 0..15
    const int b    = blockIdx.x * 16 + warp;
    const int lane = threadIdx.x & 31;
    const int grp  = lane >> 3;
    const int hp   = lane & 7;

    const uint2* E2v = (const uint2*)g_E2;      // 8 uint2 per row

    int t0 = tokens[b * SEQ + lane];
    int t1 = (lane < SEQ - 32) ? tokens[b * SEQ + 32 + lane] : 0;

    // phase 1: resolve all 13 token indices for this lane
    int toks[13];
    #pragma unroll
    for (int i = 0; i < 12; i++) {
        int idx = 4 * i + grp;
        toks[i] = (i < 8) ? __shfl_sync(0xffffffffu, t0, idx)
                          : __shfl_sync(0xffffffffu, t1, idx - 32);
    }
    toks[12] = __shfl_sync(0xffffffffu, t1, 16 + (grp & 1));   // tokens 48/49

    // phase 2: issue ALL loads (independent -> MLP = 13 per warp)
    uint2 r[13];
    #pragma unroll
    for (int i = 0; i < 12; i++)
        r[i] = __ldg(&E2v[(size_t)toks[i] * 8 + hp]);
    r[12] = (grp < 2) ? __ldg(&E2v[(size_t)toks[12] * 8 + hp])
                      : make_uint2(0u, 0u);

    // phase 3: convert + accumulate
    float4 acc = make_float4(0.f, 0.f, 0.f, 0.f);
    #pragma unroll
    for (int i = 0; i < 13; i++) {
        float2 lo = __bfloat1622float2(*reinterpret_cast<__nv_bfloat162*>(&r[i].x));
        float2 hi = __bfloat1622float2(*reinterpret_cast<__nv_bfloat162*>(&r[i].y));
        acc.x += lo.x; acc.y += lo.y; acc.z += hi.x; acc.w += hi.y;
    }

    // combine the 4 token groups (lanes {l, l^8, l^16, l^24} share hp)
    #pragma unroll
    for (int off = 8; off <= 16; off <<= 1) {
        acc.x += __shfl_xor_sync(0xffffffffu, acc.x, off);
        acc.y += __shfl_xor_sync(0xffffffffu, acc.y, off);
        acc.z += __shfl_xor_sync(0xffffffffu, acc.z, off);
        acc.w += __shfl_xor_sync(0xffffffffu, acc.w, off);
    }

    const float inv = 1.0f / (float)SEQ;
    float4 vb = ((const float4*)Vb)[hp];
    float h0 = fmaxf(acc.x * inv + vb.x, 0.f);
    float h1 = fmaxf(acc.y * inv + vb.y, 0.f);
    float h2 = fmaxf(acc.z * inv + vb.z, 0.f);
    float h3 = fmaxf(acc.w * inv + vb.w, 0.f);

    float4 w0 = ((const float4*)Ww)[hp];
    float4 w1 = ((const float4*)(Ww + HID))[hp];
    float p0 = h0 * w0.x + h1 * w0.y + h2 * w0.z + h3 * w0.w;
    float p1 = h0 * w1.x + h1 * w1.y + h2 * w1.z + h3 * w1.w;
    #pragma unroll
    for (int off = 4; off; off >>= 1) {
        p0 += __shfl_xor_sync(0xffffffffu, p0, off);
        p1 += __shfl_xor_sync(0xffffffffu, p1, off);
    }

    float e0 = p0 + Wb[0];
    float e1 = p1 + Wb[1];
    if (lane == 0) {
        out[b * OUTC + 0] = e0;
        out[b * OUTC + 1] = e1;
        sE[warp] = make_float2(e0, e1);
    }
    __syncthreads();

    // warp 0, lanes 0-15: per-CTA max + expsum over the 16 rows -> g_part
    if (warp == 0) {
        float v0 = -1e30f, v1 = -1e30f;
        if (lane < 16) { v0 = sE[lane].x; v1 = sE[lane].y; }
        float m0 = v0, m1 = v1;
        #pragma unroll
        for (int off = 8; off; off >>= 1) {
            m0 = fmaxf(m0, __shfl_xor_sync(0xffffffffu, m0, off));
            m1 = fmaxf(m1, __shfl_xor_sync(0xffffffffu, m1, off));
        }
        float s0 = (lane < 16) ? expf(v0 - m0) : 0.f;
        float s1 = (lane < 16) ? expf(v1 - m1) : 0.f;
        #pragma unroll
        for (int off = 8; off; off >>= 1) {
            s0 += __shfl_xor_sync(0xffffffffu, s0, off);
            s1 += __shfl_xor_sync(0xffffffffu, s1, off);
        }
        if (lane == 0)
            g_part[blockIdx.x] = make_float4(m0, m1, s0, s1);
    }
    __syncthreads();

    // completion counter; last CTA computes the LSE scalars only
    if (threadIdx.x == 0) {
        __threadfence();
        unsigned n = atomicAdd(&g_done, 1u);
        sLast = (n == (unsigned)(gridDim.x - 1));
    }
    __syncthreads();
    if (!sLast) return;

    __threadfence();
    const int tid = threadIdx.x;

    // 1024 partials, 2 per thread, fixed order
    float4 a0 = g_part[tid * 2];
    float4 a1 = g_part[tid * 2 + 1];
    redm[tid] = make_float2(fmaxf(a0.x, a1.x), fmaxf(a0.y, a1.y));
    __syncthreads();
    for (int s = 256; s; s >>= 1) {
        if (tid < s) {
            redm[tid].x = fmaxf(redm[tid].x, redm[tid + s].x);
            redm[tid].y = fmaxf(redm[tid].y, redm[tid + s].y);
        }
        __syncthreads();
    }
    const float M0 = redm[0].x, M1 = redm[0].y;

    float s0 = a0.z * expf(a0.x - M0) + a1.z * expf(a1.x - M0);
    float s1 = a0.w * expf(a0.y - M1) + a1.w * expf(a1.y - M1);
    reds[tid] = make_float2(s0, s1);
    __syncthreads();
    for (int s = 256; s; s >>= 1) {
        if (tid < s) {
            reds[tid].x += reds[tid + s].x;
            reds[tid].y += reds[tid + s].y;
        }
        __syncthreads();
    }
    if (tid == 0) {
        g_lse[0] = M0 + logf(reds[0].x);
        g_lse[1] = M1 + logf(reds[0].y);
    }
}

// ---------------------------------------------------------------------------
// Pass C: wide parallel apply: out[b,c] -= lse[c]. 64 CTAs x 256 threads.
// ---------------------------------------------------------------------------
__global__ __launch_bounds__(256) void apply_kernel(float* __restrict__ out)
{
    const float l0 = g_lse[0];
    const float l1 = g_lse[1];
    const int   i  = blockIdx.x * 256 + threadIdx.x;   // 16384 float2 total
    float2 v = reinterpret_cast<float2*>(out)[i];
    v.x -= l0;
    v.y -= l1;
    reinterpret_cast<float2*>(out)[i] = v;
}

extern "C" void kernel_launch(void* const* d_in, const int* in_sizes, int n_in,
                              void* d_out, int out_size)
{
    const int*   tokens = (const int*)  d_in[0];
    const float* emb    = (const float*)d_in[1];
    const float* Vw     = (const float*)d_in[2];
    const float* Vb     = (const float*)d_in[3];
    const float* Ww     = (const float*)d_in[4];
    const float* Wb     = (const float*)d_in[5];
    float* out = (float*)d_out;

    cudaFuncSetAttribute(project_kernel,
                         cudaFuncAttributeMaxDynamicSharedMemorySize, SMEM_BYTES);

    project_kernel<<<GRID, 256, SMEM_BYTES>>>(emb, Vw);
    gather_kernel<<<BATCH / 16, 512>>>(tokens, Vb, Ww, Wb, out);
    apply_kernel<<<BATCH / 256, 256>>>(out);
}

// round 15
// speedup vs baseline: 1.0588x; 1.0017x over previous
#include <cuda_runtime.h>
#include <cuda_bf16.h>
#include <math.h>
#include <stdint.h>

#define BATCH 16384
#define SEQ   50
#define DIM   300
#define HID   32
#define OUTC  2
#define VOCAB 400000

// allocation-free scratch
__device__ uint32_t g_E2[(size_t)VOCAB * (HID / 2)];   // bf16x2 table, 25.6 MB
__device__ float4   g_part[BATCH / 32];                // per-CTA {m0,m1,s0,s1}
__device__ float    g_lse[2];                          // global logsumexp
__device__ unsigned g_done;                            // gather completion ctr

// ---------------------------------------------------------------------------
// Pass A: E2[v][j] = sum_d emb[v][d] * Vw[j][d]   (400000x300 @ 300x32)
// tf32 mma.sync, 5-stage cp.async.bulk ring, 148 persistent CTAs x 256 thr,
// B fragments in registers, bf16x2 output. emb loads L2::evict_first,
// E2 stores L2::evict_last. (At its HBM floor: ~480MB emb stream @ ~6.3TB/s.)
// ---------------------------------------------------------------------------
#define TILE_R     32
#define KSTEPS     38
#define NT32       (VOCAB / TILE_R)          // 12500 tiles
#define GRID       148
#define NSTAGE     5
#define TILE_ELEMS (TILE_R * DIM)            // 9600 floats
#define TILE_BYTES (TILE_ELEMS * 4)          // 38400 B
#define PAD_ELEMS  16
#define MBAR_OFF   (NSTAGE * TILE_ELEMS + PAD_ELEMS)
#define SMEM_BYTES ((MBAR_OFF + 20) * 4)

__device__ __forceinline__ uint32_t smem_u32(const void* p) {
    return (uint32_t)__cvta_generic_to_shared(p);
}
__device__ __forceinline__ void mbar_init(uint32_t mbar, uint32_t cnt) {
    asm volatile("mbarrier.init.shared::cta.b64 [%0], %1;" :: "r"(mbar), "r"(cnt) : "memory");
}
__device__ __forceinline__ void mbar_expect_tx(uint32_t mbar, uint32_t bytes) {
    asm volatile("mbarrier.arrive.expect_tx.shared::cta.b64 _, [%0], %1;"
                 :: "r"(mbar), "r"(bytes) : "memory");
}
__device__ __forceinline__ void mbar_arrive(uint32_t mbar) {
    asm volatile("mbarrier.arrive.release.cta.shared::cta.b64 _, [%0];"
                 :: "r"(mbar) : "memory");
}
__device__ __forceinline__ void mbar_wait(uint32_t mbar, uint32_t parity) {
    asm volatile(
        "{\n\t"
        ".reg .pred P;\n\t"
        "WAIT_%=: \n\t"
        "mbarrier.try_wait.parity.acquire.cta.shared::cta.b64 P, [%0], %1, 0x989680;\n\t"
        "@P bra.uni DONE_%=;\n\t"
        "bra.uni WAIT_%=;\n\t"
        "DONE_%=: \n\t"
        "}"
        :: "r"(mbar), "r"(parity) : "memory");
}
__device__ __forceinline__ uint64_t policy_evict_first() {
    uint64_t pol;
    asm("createpolicy.fractional.L2::evict_first.b64 %0, 1.0;" : "=l"(pol));
    return pol;
}
__device__ __forceinline__ uint64_t policy_evict_last() {
    uint64_t pol;
    asm("createpolicy.fractional.L2::evict_last.b64 %0, 1.0;" : "=l"(pol));
    return pol;
}
__device__ __forceinline__ void bulk_copy_hint(uint32_t dst, const void* src,
                                               uint32_t bytes, uint32_t mbar,
                                               uint64_t pol) {
    asm volatile(
        "cp.async.bulk.shared::cta.global.mbarrier::complete_tx::bytes.L2::cache_hint "
        "[%0], [%1], %2, [%3], %4;"
        :: "r"(dst), "l"(src), "r"(bytes), "r"(mbar), "l"(pol) : "memory");
}
__device__ __forceinline__ void st_hint(uint32_t* p, uint32_t v, uint64_t pol) {
    asm volatile("st.global.L2::cache_hint.b32 [%0], %1, %2;"
                 :: "l"(p), "r"(v), "l"(pol) : "memory");
}
__device__ __forceinline__ void mma_tf32(
    float acc[4], uint32_t a0, uint32_t a1, uint32_t a2, uint32_t a3,
    uint32_t b0, uint32_t b1)
{
    asm volatile(
        "mma.sync.aligned.m16n8k8.row.col.f32.tf32.tf32.f32 "
        "{%0,%1,%2,%3}, {%4,%5,%6,%7}, {%8,%9}, {%0,%1,%2,%3};\n"
        : "+f"(acc[0]), "+f"(acc[1]), "+f"(acc[2]), "+f"(acc[3])
        : "r"(a0), "r"(a1), "r"(a2), "r"(a3), "r"(b0), "r"(b1));
}
__device__ __forceinline__ uint32_t pack_bf16x2(float lo, float hi) {
    __nv_bfloat162 v = __float22bfloat162_rn(make_float2(lo, hi));
    return *reinterpret_cast<uint32_t*>(&v);
}

__global__ __launch_bounds__(256) void project_kernel(
    const float* __restrict__ emb,
    const float* __restrict__ Vw)
{
    extern __shared__ float smem[];
    const uint32_t mbarBase  = smem_u32(smem + MBAR_OFF);   // full[0..4]
    const uint32_t emptyBase = mbarBase + NSTAGE * 8;       // empty[0..4]

    const int tid  = threadIdx.x;
    const int warp = tid >> 5;
    const int lane = tid & 31;
    const int g4   = lane >> 2;
    const int tg   = lane & 3;

    const int warpRow = warp >> 2;
    const int colQuad = warp & 3;
    const int aRow    = warpRow * 16 + g4;

    if (blockIdx.x == 0 && tid == 0) g_done = 0;   // reset gather's counter

    const uint64_t polF = policy_evict_first();
    const uint64_t polL = policy_evict_last();

    if (tid == 0) {
        #pragma unroll
        for (int i = 0; i < NSTAGE; i++) {
            mbar_init(mbarBase  + i * 8, 1);
            mbar_init(emptyBase + i * 8, 8);
        }
        asm volatile("fence.proxy.async.shared::cta;" ::: "memory");
    }
    if (tid < PAD_ELEMS)
        smem[NSTAGE * TILE_ELEMS + tid] = 0.0f;
    __syncthreads();

    const int bid = blockIdx.x;

    if (tid == 0) {
        #pragma unroll
        for (int s = 0; s < NSTAGE; s++) {
            int tt = bid + s * GRID;
            if (tt < NT32) {
                mbar_expect_tx(mbarBase + s * 8, TILE_BYTES);
                bulk_copy_hint(smem_u32(smem + s * TILE_ELEMS),
                               emb + (size_t)tt * TILE_ELEMS, TILE_BYTES,
                               mbarBase + s * 8, polF);
            }
        }
    }

    // B fragments straight from gmem into registers (once)
    uint2 breg[KSTEPS];
    {
        const int n = colQuad * 8 + g4;
        const float* vwr = Vw + n * DIM;
        #pragma unroll
        for (int ks = 0; ks < KSTEPS; ks++) {
            int k = ks * 8 + tg;
            breg[ks].x = (k     < DIM) ? __float_as_uint(vwr[k])     : 0u;
            breg[ks].y = (k + 4 < DIM) ? __float_as_uint(vwr[k + 4]) : 0u;
        }
    }

    uint32_t ph0 = 0, ph1 = 0, ph2 = 0, ph3 = 0, ph4 = 0;
    uint32_t pe0 = 0, pe1 = 0, pe2 = 0, pe3 = 0, pe4 = 0;

    int t = bid;
    while (t < NT32) {
        #pragma unroll
        for (int s = 0; s < NSTAGE; s++) {
            if (t < NT32) {
                const uint32_t fullb  = mbarBase  + s * 8;
                const uint32_t emptyb = emptyBase + s * 8;

                uint32_t phv = (s == 0) ? ph0 : (s == 1) ? ph1 : (s == 2) ? ph2
                             : (s == 3) ? ph3 : ph4;
                mbar_wait(fullb, phv);
                if      (s == 0) ph0 ^= 1;
                else if (s == 1) ph1 ^= 1;
                else if (s == 2) ph2 ^= 1;
                else if (s == 3) ph3 ^= 1;
                else             ph4 ^= 1;

                const uint32_t* A =
                    (const uint32_t*)(smem + s * TILE_ELEMS) + aRow * DIM + tg;

                float accE[4] = {0.f, 0.f, 0.f, 0.f};
                float accO[4] = {0.f, 0.f, 0.f, 0.f};

                #pragma unroll
                for (int ks = 0; ks < KSTEPS; ks += 2) {
                    {
                        const uint32_t* Ap = A + ks * 8;
                        mma_tf32(accE, Ap[0], Ap[8 * DIM], Ap[4], Ap[8 * DIM + 4],
                                 breg[ks].x, breg[ks].y);
                    }
                    {
                        const uint32_t* Ap = A + (ks + 1) * 8;
                        mma_tf32(accO, Ap[0], Ap[8 * DIM], Ap[4], Ap[8 * DIM + 4],
                                 breg[ks + 1].x, breg[ks + 1].y);
                    }
                }

                if (lane == 0) mbar_arrive(emptyb);

                int r0  = t * TILE_R + warpRow * 16 + g4;
                int cp  = colQuad * 4 + tg;
                st_hint(&g_E2[(size_t)r0 * (HID / 2) + cp],
                        pack_bf16x2(accE[0] + accO[0], accE[1] + accO[1]), polL);
                st_hint(&g_E2[(size_t)(r0 + 8) * (HID / 2) + cp],
                        pack_bf16x2(accE[2] + accO[2], accE[3] + accO[3]), polL);

                int tload = t + NSTAGE * GRID;
                if (tid == 0 && tload < NT32) {
                    uint32_t pev = (s == 0) ? pe0 : (s == 1) ? pe1 : (s == 2) ? pe2
                                 : (s == 3) ? pe3 : pe4;
                    mbar_wait(emptyb, pev);
                    if      (s == 0) pe0 ^= 1;
                    else if (s == 1) pe1 ^= 1;
                    else if (s == 2) pe2 ^= 1;
                    else if (s == 3) pe3 ^= 1;
                    else             pe4 ^= 1;
                    mbar_expect_tx(fullb, TILE_BYTES);
                    bulk_copy_hint(smem_u32(smem + s * TILE_ELEMS),
                                   emb + (size_t)tload * TILE_ELEMS, TILE_BYTES,
                                   fullb, polF);
                }
                t += GRID;
            }
        }
    }
}

// ---------------------------------------------------------------------------
// Pass B: gather bf16 E2, mean-pool, relu head -> logits + per-CTA partial.
// R15: 1024 threads / 32 rows per CTA (grid 512). Two-phase loads (MLP=13).
// All reductions are warp-shuffle trees (3 __syncthreads total in the
// last-CTA global reduce instead of an 18-step smem ladder).
// ---------------------------------------------------------------------------
__global__ __launch_bounds__(1024) void gather_kernel(
    const int*   __restrict__ tokens,
    const float* __restrict__ Vb,
    const float* __restrict__ Ww,
    const float* __restrict__ Wb,
    float*       __restrict__ out)
{
    __shared__ float2 sE[32];
    __shared__ bool   sLast;
    __shared__ float2 sWm[16];
    __shared__ float2 sWs[16];
    __shared__ float2 sM;

    const int warp = threadIdx.x >> 5;          // 0..31 = row within CTA
    const int b    = blockIdx.x * 32 + warp;
    const int lane = threadIdx.x & 31;
    const int grp  = lane >> 3;
    const int hp   = lane & 7;

    const uint2* E2v = (const uint2*)g_E2;      // 8 uint2 per row

    int t0 = tokens[b * SEQ + lane];
    int t1 = (lane < SEQ - 32) ? tokens[b * SEQ + 32 + lane] : 0;

    // phase 1: resolve all 13 token indices for this lane
    int toks[13];
    #pragma unroll
    for (int i = 0; i < 12; i++) {
        int idx = 4 * i + grp;
        toks[i] = (i < 8) ? __shfl_sync(0xffffffffu, t0, idx)
                          : __shfl_sync(0xffffffffu, t1, idx - 32);
    }
    toks[12] = __shfl_sync(0xffffffffu, t1, 16 + (grp & 1));   // tokens 48/49

    // phase 2: issue ALL loads (independent -> MLP = 13 per warp)
    uint2 r[13];
    #pragma unroll
    for (int i = 0; i < 12; i++)
        r[i] = __ldg(&E2v[(size_t)toks[i] * 8 + hp]);
    r[12] = (grp < 2) ? __ldg(&E2v[(size_t)toks[12] * 8 + hp])
                      : make_uint2(0u, 0u);

    // phase 3: convert + accumulate
    float4 acc = make_float4(0.f, 0.f, 0.f, 0.f);
    #pragma unroll
    for (int i = 0; i < 13; i++) {
        float2 lo = __bfloat1622float2(*reinterpret_cast<__nv_bfloat162*>(&r[i].x));
        float2 hi = __bfloat1622float2(*reinterpret_cast<__nv_bfloat162*>(&r[i].y));
        acc.x += lo.x; acc.y += lo.y; acc.z += hi.x; acc.w += hi.y;
    }

    // combine the 4 token groups (lanes {l, l^8, l^16, l^24} share hp)
    #pragma unroll
    for (int off = 8; off <= 16; off <<= 1) {
        acc.x += __shfl_xor_sync(0xffffffffu, acc.x, off);
        acc.y += __shfl_xor_sync(0xffffffffu, acc.y, off);
        acc.z += __shfl_xor_sync(0xffffffffu, acc.z, off);
        acc.w += __shfl_xor_sync(0xffffffffu, acc.w, off);
    }

    const float inv = 1.0f / (float)SEQ;
    float4 vb = ((const float4*)Vb)[hp];
    float h0 = fmaxf(acc.x * inv + vb.x, 0.f);
    float h1 = fmaxf(acc.y * inv + vb.y, 0.f);
    float h2 = fmaxf(acc.z * inv + vb.z, 0.f);
    float h3 = fmaxf(acc.w * inv + vb.w, 0.f);

    float4 w0 = ((const float4*)Ww)[hp];
    float4 w1 = ((const float4*)(Ww + HID))[hp];
    float p0 = h0 * w0.x + h1 * w0.y + h2 * w0.z + h3 * w0.w;
    float p1 = h0 * w1.x + h1 * w1.y + h2 * w1.z + h3 * w1.w;
    #pragma unroll
    for (int off = 4; off; off >>= 1) {
        p0 += __shfl_xor_sync(0xffffffffu, p0, off);
        p1 += __shfl_xor_sync(0xffffffffu, p1, off);
    }

    float e0 = p0 + Wb[0];
    float e1 = p1 + Wb[1];
    if (lane == 0) {
        out[b * OUTC + 0] = e0;
        out[b * OUTC + 1] = e1;
        sE[warp] = make_float2(e0, e1);
    }
    __syncthreads();

    // warp 0: per-CTA max + expsum over 32 rows via shuffle tree -> g_part
    if (warp == 0) {
        float v0 = sE[lane].x, v1 = sE[lane].y;
        float m0 = v0, m1 = v1;
        #pragma unroll
        for (int off = 16; off; off >>= 1) {
            m0 = fmaxf(m0, __shfl_xor_sync(0xffffffffu, m0, off));
            m1 = fmaxf(m1, __shfl_xor_sync(0xffffffffu, m1, off));
        }
        float s0 = expf(v0 - m0);
        float s1 = expf(v1 - m1);
        #pragma unroll
        for (int off = 16; off; off >>= 1) {
            s0 += __shfl_xor_sync(0xffffffffu, s0, off);
            s1 += __shfl_xor_sync(0xffffffffu, s1, off);
        }
        if (lane == 0)
            g_part[blockIdx.x] = make_float4(m0, m1, s0, s1);
    }
    __syncthreads();

    // completion counter; last CTA computes the LSE scalars only
    if (threadIdx.x == 0) {
        __threadfence();
        unsigned n = atomicAdd(&g_done, 1u);
        sLast = (n == (unsigned)(gridDim.x - 1));
    }
    __syncthreads();
    if (!sLast) return;

    __threadfence();

    // 512 partials: warps 0-15 each reduce 32 via shuffle, then warp 0 combines
    if (warp < 16) {
        float4 a = g_part[warp * 32 + lane];
        float m0 = a.x, m1 = a.y;
        #pragma unroll
        for (int off = 16; off; off >>= 1) {
            m0 = fmaxf(m0, __shfl_xor_sync(0xffffffffu, m0, off));
            m1 = fmaxf(m1, __shfl_xor_sync(0xffffffffu, m1, off));
        }
        if (lane == 0) sWm[warp] = make_float2(m0, m1);
    }
    __syncthreads();
    if (warp == 0) {
        float m0 = (lane < 16) ? sWm[lane].x : -1e30f;
        float m1 = (lane < 16) ? sWm[lane].y : -1e30f;
        #pragma unroll
        for (int off = 8; off; off >>= 1) {
            m0 = fmaxf(m0, __shfl_xor_sync(0xffffffffu, m0, off));
            m1 = fmaxf(m1, __shfl_xor_sync(0xffffffffu, m1, off));
        }
        if (lane == 0) sM = make_float2(m0, m1);
    }
    __syncthreads();
    const float M0 = sM.x, M1 = sM.y;

    if (warp < 16) {
        float4 a = g_part[warp * 32 + lane];
        float s0 = a.z * expf(a.x - M0);
        float s1 = a.w * expf(a.y - M1);
        #pragma unroll
        for (int off = 16; off; off >>= 1) {
            s0 += __shfl_xor_sync(0xffffffffu, s0, off);
            s1 += __shfl_xor_sync(0xffffffffu, s1, off);
        }
        if (lane == 0) sWs[warp] = make_float2(s0, s1);
    }
    __syncthreads();
    if (warp == 0) {
        float s0 = (lane < 16) ? sWs[lane].x : 0.f;
        float s1 = (lane < 16) ? sWs[lane].y : 0.f;
        #pragma unroll
        for (int off = 8; off; off >>= 1) {
            s0 += __shfl_xor_sync(0xffffffffu, s0, off);
            s1 += __shfl_xor_sync(0xffffffffu, s1, off);
        }
        if (lane == 0) {
            g_lse[0] = M0 + logf(s0);
            g_lse[1] = M1 + logf(s1);
        }
    }
}

// ---------------------------------------------------------------------------
// Pass C: wide parallel apply: out[b,c] -= lse[c]. 16 CTAs x 512, float4.
// ---------------------------------------------------------------------------
__global__ __launch_bounds__(512) void apply_kernel(float* __restrict__ out)
{
    const float l0 = g_lse[0];
    const float l1 = g_lse[1];
    const int   i  = blockIdx.x * 512 + threadIdx.x;   // 8192 float4 total
    float4 v = reinterpret_cast<float4*>(out)[i];
    v.x -= l0; v.y -= l1; v.z -= l0; v.w -= l1;
    reinterpret_cast<float4*>(out)[i] = v;
}

extern "C" void kernel_launch(void* const* d_in, const int* in_sizes, int n_in,
                              void* d_out, int out_size)
{
    const int*   tokens = (const int*)  d_in[0];
    const float* emb    = (const float*)d_in[1];
    const float* Vw     = (const float*)d_in[2];
    const float* Vb     = (const float*)d_in[3];
    const float* Ww     = (const float*)d_in[4];
    const float* Wb     = (const float*)d_in[5];
    float* out = (float*)d_out;

    cudaFuncSetAttribute(project_kernel,
                         cudaFuncAttributeMaxDynamicSharedMemorySize, SMEM_BYTES);

    project_kernel<<<GRID, 256, SMEM_BYTES>>>(emb, Vw);
    gather_kernel<<<BATCH / 32, 1024>>>(tokens, Vb, Ww, Wb, out);
    apply_kernel<<<16, 512>>>(out);
}